// round 3
// baseline (speedup 1.0000x reference)
#include <cuda_runtime.h>
#include <cuda_bf16.h>
#include <cstddef>

// Problem constants
#define NB   8
#define CD   256
#define HH   96
#define WW   96
#define HWSZ (HH*WW)          // 9216
#define TT   32
#define VV   256
#define TV   (TT*VV)          // 8192
#define INV_TEMP 2.0f         // 1/0.5
#define SHIFT    2.0f         // structural row max: dot_ii = ||f||^2 / tau = 2

// Scratch (static device globals; no runtime allocation)
__device__ float g_F[TV * CD];                     // normalized features, row-major (8192 x 256), 8 MB
__device__ float g_dot[(size_t)TV * TV];           // Gram matrix * 1/tau, 256 MB

// ---------------------------------------------------------------------------
// Kernel 0: zero the output scalar
// ---------------------------------------------------------------------------
__global__ void init_out_kernel(float* out) { out[0] = 0.0f; }

// ---------------------------------------------------------------------------
// Kernel 1: gather V pixels per (t) row, L2-normalize along C.
// One block per row i in [0, TV); thread c handles channel c.
// ---------------------------------------------------------------------------
__global__ void gather_norm_kernel(const float* __restrict__ features,
                                   const int*   __restrict__ batch_inds,
                                   const int*   __restrict__ sample_inds)
{
    int i = blockIdx.x;          // row = t*V + v
    int c = threadIdx.x;         // channel
    int t = i >> 8;              // V = 256
    int b = batch_inds[t];
    int s = sample_inds[i];

    float x = features[((size_t)b * CD + c) * HWSZ + (size_t)s];

    __shared__ float red[256];
    red[c] = x * x;
    __syncthreads();
    #pragma unroll
    for (int ofs = 128; ofs > 0; ofs >>= 1) {
        if (c < ofs) red[c] += red[c + ofs];
        __syncthreads();
    }
    __shared__ float s_inv;
    if (c == 0) {
        float nrm = fmaxf(sqrtf(red[0]), 1e-12f);
        s_inv = 1.0f / nrm;
    }
    __syncthreads();
    g_F[(size_t)i * CD + c] = x * s_inv;
}

// ---------------------------------------------------------------------------
// Kernel 2: D = (F F^T) * INV_TEMP, fp32 SIMT tiled GEMM.
// BM = BN = 128, BK = 8, 256 threads, 8x8 outputs/thread in 2x2 groups of 4x4.
// ---------------------------------------------------------------------------
#define BM 128
#define BN 128
#define BK 8
#define SPAD 4

__global__ __launch_bounds__(256) void gemm_kernel()
{
    __shared__ float As[BK][BM + SPAD];
    __shared__ float Bs[BK][BN + SPAD];

    const int tid = threadIdx.x;
    const int tx  = tid & 15;          // 0..15 (column group)
    const int ty  = tid >> 4;          // 0..15 (row group)
    const int i0  = blockIdx.y * BM;
    const int j0  = blockIdx.x * BN;

    // load mapping: each thread loads one float4 for A and one for B per k-tile
    const int lrow = tid >> 1;         // 0..127
    const int lk4  = (tid & 1) * 4;    // 0 or 4
    const float* Aptr = g_F + (size_t)(i0 + lrow) * CD + lk4;
    const float* Bptr = g_F + (size_t)(j0 + lrow) * CD + lk4;

    float acc[8][8];
    #pragma unroll
    for (int r = 0; r < 8; r++)
        #pragma unroll
        for (int c = 0; c < 8; c++) acc[r][c] = 0.0f;

    for (int kt = 0; kt < CD; kt += BK) {
        float4 a = *(const float4*)(Aptr + kt);
        float4 b = *(const float4*)(Bptr + kt);
        __syncthreads();
        As[lk4 + 0][lrow] = a.x; As[lk4 + 1][lrow] = a.y;
        As[lk4 + 2][lrow] = a.z; As[lk4 + 3][lrow] = a.w;
        Bs[lk4 + 0][lrow] = b.x; Bs[lk4 + 1][lrow] = b.y;
        Bs[lk4 + 2][lrow] = b.z; Bs[lk4 + 3][lrow] = b.w;
        __syncthreads();

        #pragma unroll
        for (int k = 0; k < BK; k++) {
            float ar[8], br[8];
            *(float4*)(ar)     = *(const float4*)&As[k][ty * 4];
            *(float4*)(ar + 4) = *(const float4*)&As[k][64 + ty * 4];
            *(float4*)(br)     = *(const float4*)&Bs[k][tx * 4];
            *(float4*)(br + 4) = *(const float4*)&Bs[k][64 + tx * 4];
            #pragma unroll
            for (int r = 0; r < 8; r++)
                #pragma unroll
                for (int c = 0; c < 8; c++)
                    acc[r][c] = fmaf(ar[r], br[c], acc[r][c]);
        }
    }

    // write out, scaled by 1/temperature
    #pragma unroll
    for (int q = 0; q < 8; q++) {
        int irow = i0 + ((q < 4) ? (ty * 4 + q) : (64 + ty * 4 + (q - 4)));
        float4 v0 = make_float4(INV_TEMP * acc[q][0], INV_TEMP * acc[q][1],
                                INV_TEMP * acc[q][2], INV_TEMP * acc[q][3]);
        float4 v1 = make_float4(INV_TEMP * acc[q][4], INV_TEMP * acc[q][5],
                                INV_TEMP * acc[q][6], INV_TEMP * acc[q][7]);
        *(float4*)&g_dot[(size_t)irow * TV + j0 + tx * 4]      = v0;
        *(float4*)&g_dot[(size_t)irow * TV + j0 + 64 + tx * 4] = v1;
    }
}

// ---------------------------------------------------------------------------
// Kernel 3: per-row SupCon reduction. One block (256 thr) per row; the row
// (8192 floats) lives in registers (32/thread). Uses the shift-invariance
// of log_prob to replace the row max with the constant SHIFT = 2.
// loss contribution: -(1/TV) * (sum_pos [l - log(exp(l)+neg_sum)]) / pos_cnt
// ---------------------------------------------------------------------------
__global__ __launch_bounds__(256) void rowpass_kernel(const int* __restrict__ labels,
                                                      float* __restrict__ out)
{
    __shared__ int   labs[TT];
    __shared__ float red[256];
    __shared__ float s_neg;

    const int tid = threadIdx.x;
    const int i   = blockIdx.x;
    if (tid < TT) labs[tid] = labels[tid];
    __syncthreads();

    const int li = labs[i >> 8];
    const float* row = g_dot + (size_t)i * TV;

    float r[32];
    float negs = 0.0f;
    #pragma unroll
    for (int j0 = 0; j0 < 32; j0++) {
        float d = row[tid + j0 * 256];
        r[j0] = d;
        if (labs[j0] != li) negs += expf(d - SHIFT);
    }

    // block reduce negs
    red[tid] = negs;
    __syncthreads();
    #pragma unroll
    for (int ofs = 128; ofs > 0; ofs >>= 1) {
        if (tid < ofs) red[tid] += red[tid + ofs];
        __syncthreads();
    }
    if (tid == 0) s_neg = red[0];
    __syncthreads();
    const float neg_sum = s_neg;

    // positive pass (from registers)
    float psum = 0.0f;
    int   pcnt = 0;
    #pragma unroll
    for (int j0 = 0; j0 < 32; j0++) {
        int j = tid + j0 * 256;
        if (labs[j0] == li && j != i) {
            float l = r[j0] - SHIFT;
            psum += l - logf(expf(l) + neg_sum);
            pcnt++;
        }
    }

    __syncthreads();
    red[tid] = psum;
    __syncthreads();
    #pragma unroll
    for (int ofs = 128; ofs > 0; ofs >>= 1) {
        if (tid < ofs) red[tid] += red[tid + ofs];
        __syncthreads();
    }
    float psum_tot = red[0];
    __syncthreads();
    red[tid] = (float)pcnt;
    __syncthreads();
    #pragma unroll
    for (int ofs = 128; ofs > 0; ofs >>= 1) {
        if (tid < ofs) red[tid] += red[tid + ofs];
        __syncthreads();
    }
    if (tid == 0) {
        float pcnt_tot = red[0];
        float mean_lp  = psum_tot / fmaxf(pcnt_tot, 1e-10f);
        atomicAdd(out, -mean_lp / (float)TV);
    }
}

// ---------------------------------------------------------------------------
extern "C" void kernel_launch(void* const* d_in, const int* in_sizes, int n_in,
                              void* d_out, int out_size)
{
    const float* features    = (const float*)d_in[0];
    const int*   batch_inds  = (const int*)d_in[1];
    const int*   sample_inds = (const int*)d_in[2];
    const int*   labels      = (const int*)d_in[3];
    float*       out         = (float*)d_out;

    init_out_kernel<<<1, 1>>>(out);
    gather_norm_kernel<<<TV, 256>>>(features, batch_inds, sample_inds);
    dim3 grid(TV / BN, TV / BM);
    gemm_kernel<<<grid, 256>>>();
    rowpass_kernel<<<TV, 256>>>(labels, out);
}

// round 6
// speedup vs baseline: 3.0567x; 3.0567x over previous
#include <cuda_runtime.h>
#include <cuda_bf16.h>
#include <cstdint>
#include <cstddef>

// Problem constants
#define NB   8
#define CD   256
#define HWSZ 9216
#define TT   32
#define VV   256
#define TV   8192
#define INV_TEMP 2.0f
#define SHIFT    2.0f

// GEMM tiling
#define TM 128
#define TN 128
#define PITCHB 528                    // bytes per SMEM tile row (264 bf16): 33*16B
#define TILE_BYTES (128 * PITCHB)     // 67584
#define SMEM_TOTAL (2 * TILE_BYTES)   // 135168

// Scratch
__device__ __nv_bfloat16 g_Fb[(size_t)TV * CD];   // normalized feats, bf16 (4 MB)
__device__ float g_dot[(size_t)TV * TV];          // Gram * 1/tau (256 MB)

// ---------------------------------------------------------------------------
__global__ void init_out_kernel(float* out) { out[0] = 0.0f; }

// ---------------------------------------------------------------------------
// Gather + L2-normalize -> bf16 feature matrix (8192 x 256)
// ---------------------------------------------------------------------------
__global__ void gather_norm_kernel(const float* __restrict__ features,
                                   const int*   __restrict__ batch_inds,
                                   const int*   __restrict__ sample_inds)
{
    int i = blockIdx.x;
    int c = threadIdx.x;
    int b = batch_inds[i >> 8];
    int s = sample_inds[i];

    float x = features[((size_t)b * CD + c) * HWSZ + (size_t)s];

    __shared__ float red[256];
    red[c] = x * x;
    __syncthreads();
    #pragma unroll
    for (int ofs = 128; ofs > 0; ofs >>= 1) {
        if (c < ofs) red[c] += red[c + ofs];
        __syncthreads();
    }
    __shared__ float s_inv;
    if (c == 0) s_inv = 1.0f / fmaxf(sqrtf(red[0]), 1e-12f);
    __syncthreads();
    g_Fb[(size_t)i * CD + c] = __float2bfloat16(x * s_inv);
}

// ---------------------------------------------------------------------------
__device__ __forceinline__ uint32_t smem_u32(const void* p) {
    uint32_t a;
    asm("{ .reg .u64 t; cvta.to.shared.u64 t, %1; cvt.u32.u64 %0, t; }"
        : "=r"(a) : "l"(p));
    return a;
}

__device__ __forceinline__ void ldsm_x4(uint32_t* r, uint32_t addr) {
    asm volatile("ldmatrix.sync.aligned.m8n8.x4.shared.b16 {%0,%1,%2,%3}, [%4];"
                 : "=r"(r[0]), "=r"(r[1]), "=r"(r[2]), "=r"(r[3]) : "r"(addr));
}

__device__ __forceinline__ void mma16816(float* c, const uint32_t* a,
                                         uint32_t b0, uint32_t b1) {
    asm volatile(
        "mma.sync.aligned.m16n8k16.row.col.f32.bf16.bf16.f32 "
        "{%0,%1,%2,%3}, {%4,%5,%6,%7}, {%8,%9}, {%0,%1,%2,%3};"
        : "+f"(c[0]), "+f"(c[1]), "+f"(c[2]), "+f"(c[3])
        : "r"(a[0]), "r"(a[1]), "r"(a[2]), "r"(a[3]), "r"(b0), "r"(b1));
}

// Copy a 128x256 bf16 tile (rows row0..row0+127 of g_Fb) into padded SMEM.
__device__ __forceinline__ void load_tile(char* dst, int row0, int tid)
{
    #pragma unroll
    for (int it = 0; it < 16; it++) {
        int chunk = tid + it * 256;        // 4096 x 16B chunks
        int r   = chunk >> 5;              // 32 chunks (512B) per row
        int c16 = chunk & 31;
        uint4 v = *(const uint4*)(g_Fb + (size_t)(row0 + r) * CD + c16 * 8);
        *(uint4*)(dst + r * PITCHB + c16 * 16) = v;
    }
}

// ---------------------------------------------------------------------------
// Kernel 2: D = (F F^T) * INV_TEMP via bf16 mma.sync (HMMA).
// CTA = 128x128 tile, 8 warps (4x2), warp tile 32x64.
// ---------------------------------------------------------------------------
__global__ __launch_bounds__(256)
void gram_mma_kernel()
{
    extern __shared__ char smem[];
    char* At = smem;
    char* Bt = smem + TILE_BYTES;

    const int tid = threadIdx.x;
    const int wid = tid >> 5;
    const int lid = tid & 31;
    const int i0  = blockIdx.y * TM;
    const int j0  = blockIdx.x * TN;

    load_tile(At, i0, tid);
    load_tile(Bt, j0, tid);
    __syncthreads();

    const int wm = (wid & 3) * 32;     // warp M offset in tile
    const int wn = (wid >> 2) * 64;    // warp N offset in tile

    const uint32_t a_base = smem_u32(At) + (wm + (lid & 15)) * PITCHB + (lid >> 4) * 16;
    const uint32_t b_base = smem_u32(Bt) + (wn + (lid & 15)) * PITCHB + (lid >> 4) * 16;

    float acc[2][8][4];
    #pragma unroll
    for (int mi = 0; mi < 2; mi++)
        #pragma unroll
        for (int nj = 0; nj < 8; nj++)
            #pragma unroll
            for (int q = 0; q < 4; q++) acc[mi][nj][q] = 0.0f;

    #pragma unroll
    for (int ks = 0; ks < 16; ks++) {
        const int kb = ks * 32;                    // 16 bf16 = 32 bytes
        uint32_t a[2][4], b[4][4];
        #pragma unroll
        for (int mi = 0; mi < 2; mi++)
            ldsm_x4(a[mi], a_base + mi * 16 * PITCHB + kb);
        #pragma unroll
        for (int nb = 0; nb < 4; nb++)
            ldsm_x4(b[nb], b_base + nb * 16 * PITCHB + kb);
        #pragma unroll
        for (int mi = 0; mi < 2; mi++)
            #pragma unroll
            for (int nj = 0; nj < 8; nj++)
                mma16816(acc[mi][nj], a[mi],
                         b[nj >> 1][nj & 1], b[nj >> 1][2 + (nj & 1)]);
    }

    // Epilogue: scale by 1/tau, direct coalesced float2 stores.
    #pragma unroll
    for (int mi = 0; mi < 2; mi++) {
        #pragma unroll
        for (int nj = 0; nj < 8; nj++) {
            int r = i0 + wm + mi * 16 + (lid >> 2);
            int c = j0 + wn + nj * 8 + (lid & 3) * 2;
            float2 v0 = make_float2(INV_TEMP * acc[mi][nj][0],
                                    INV_TEMP * acc[mi][nj][1]);
            float2 v1 = make_float2(INV_TEMP * acc[mi][nj][2],
                                    INV_TEMP * acc[mi][nj][3]);
            *(float2*)&g_dot[(size_t)r * TV + c]       = v0;
            *(float2*)&g_dot[(size_t)(r + 8) * TV + c] = v1;
        }
    }
}

// ---------------------------------------------------------------------------
// Kernel 3: per-row SupCon reduction (validated baseline).
// ---------------------------------------------------------------------------
__global__ __launch_bounds__(256) void rowpass_kernel(const int* __restrict__ labels,
                                                      float* __restrict__ out)
{
    __shared__ int   labs[TT];
    __shared__ float red[256];
    __shared__ float s_neg;

    const int tid = threadIdx.x;
    const int i   = blockIdx.x;
    if (tid < TT) labs[tid] = labels[tid];
    __syncthreads();

    const int li = labs[i >> 8];
    const float* row = g_dot + (size_t)i * TV;

    float r[32];
    float negs = 0.0f;
    #pragma unroll
    for (int j0 = 0; j0 < 32; j0++) {
        float d = row[tid + j0 * 256];
        r[j0] = d;
        if (labs[j0] != li) negs += expf(d - SHIFT);
    }

    red[tid] = negs;
    __syncthreads();
    #pragma unroll
    for (int ofs = 128; ofs > 0; ofs >>= 1) {
        if (tid < ofs) red[tid] += red[tid + ofs];
        __syncthreads();
    }
    if (tid == 0) s_neg = red[0];
    __syncthreads();
    const float neg_sum = s_neg;

    float psum = 0.0f;
    int   pcnt = 0;
    #pragma unroll
    for (int j0 = 0; j0 < 32; j0++) {
        int j = tid + j0 * 256;
        if (labs[j0] == li && j != i) {
            float l = r[j0] - SHIFT;
            psum += l - logf(expf(l) + neg_sum);
            pcnt++;
        }
    }

    __syncthreads();
    red[tid] = psum;
    __syncthreads();
    #pragma unroll
    for (int ofs = 128; ofs > 0; ofs >>= 1) {
        if (tid < ofs) red[tid] += red[tid + ofs];
        __syncthreads();
    }
    float psum_tot = red[0];
    __syncthreads();
    red[tid] = (float)pcnt;
    __syncthreads();
    #pragma unroll
    for (int ofs = 128; ofs > 0; ofs >>= 1) {
        if (tid < ofs) red[tid] += red[tid + ofs];
        __syncthreads();
    }
    if (tid == 0) {
        float pcnt_tot = red[0];
        float mean_lp  = psum_tot / fmaxf(pcnt_tot, 1e-10f);
        atomicAdd(out, -mean_lp / (float)TV);
    }
}

// ---------------------------------------------------------------------------
extern "C" void kernel_launch(void* const* d_in, const int* in_sizes, int n_in,
                              void* d_out, int out_size)
{
    const float* features    = (const float*)d_in[0];
    const int*   batch_inds  = (const int*)d_in[1];
    const int*   sample_inds = (const int*)d_in[2];
    const int*   labels      = (const int*)d_in[3];
    float*       out         = (float*)d_out;

    cudaFuncSetAttribute(gram_mma_kernel,
                         cudaFuncAttributeMaxDynamicSharedMemorySize, SMEM_TOTAL);

    init_out_kernel<<<1, 1>>>(out);
    gather_norm_kernel<<<TV, 256>>>(features, batch_inds, sample_inds);
    dim3 grid(TV / TN, TV / TM);
    gram_mma_kernel<<<grid, 256, SMEM_TOTAL>>>();
    rowpass_kernel<<<TV, 256>>>(labels, out);
}

// round 7
// speedup vs baseline: 4.9074x; 1.6054x over previous
#include <cuda_runtime.h>
#include <cuda_bf16.h>
#include <cstdint>
#include <cstddef>

// Problem constants
#define NB   8
#define CD   256
#define HWSZ 9216
#define TT   32
#define VV   256
#define TV   8192
#define NT   64                       // 8192 / 128 tiles per dim
#define INV_TEMP 2.0f
#define SHIFT    2.0f

// GEMM tiling
#define TM 128
#define TN 128
#define PITCHB 528                    // bytes per SMEM tile row (264 bf16)
#define TILE_BYTES (128 * PITCHB)     // 67584
#define STAGE_PITCH 129               // floats; stage reuses the A-tile region
#define OFF_ROWNEG (2 * TILE_BYTES)
#define OFF_COLNEG (2 * TILE_BYTES + 512)
#define SMEM_TOTAL (2 * TILE_BYTES + 1024)   // 136192 bytes

// Scratch
__device__ __nv_bfloat16 g_Fb[(size_t)TV * CD];   // normalized feats, bf16 (4 MB)
__device__ float g_dot[(size_t)TV * TV];          // only same-label tiles written
__device__ float g_neg[TV];                       // per-row sum of exp(l) over negatives

// ---------------------------------------------------------------------------
__global__ void zero_kernel(float* out) {
    int i = blockIdx.x * blockDim.x + threadIdx.x;
    if (i < TV) g_neg[i] = 0.0f;
    if (i == 0) out[0] = 0.0f;
}

// ---------------------------------------------------------------------------
// Gather + L2-normalize -> bf16 feature matrix (8192 x 256)
// ---------------------------------------------------------------------------
__global__ void gather_norm_kernel(const float* __restrict__ features,
                                   const int*   __restrict__ batch_inds,
                                   const int*   __restrict__ sample_inds)
{
    int i = blockIdx.x;
    int c = threadIdx.x;
    int b = batch_inds[i >> 8];
    int s = sample_inds[i];

    float x = features[((size_t)b * CD + c) * HWSZ + (size_t)s];

    __shared__ float red[256];
    red[c] = x * x;
    __syncthreads();
    #pragma unroll
    for (int ofs = 128; ofs > 0; ofs >>= 1) {
        if (c < ofs) red[c] += red[c + ofs];
        __syncthreads();
    }
    __shared__ float s_inv;
    if (c == 0) s_inv = 1.0f / fmaxf(sqrtf(red[0]), 1e-12f);
    __syncthreads();
    g_Fb[(size_t)i * CD + c] = __float2bfloat16(x * s_inv);
}

// ---------------------------------------------------------------------------
__device__ __forceinline__ uint32_t smem_u32(const void* p) {
    uint32_t a;
    asm("{ .reg .u64 t; cvta.to.shared.u64 t, %1; cvt.u32.u64 %0, t; }"
        : "=r"(a) : "l"(p));
    return a;
}

__device__ __forceinline__ void ldsm_x4(uint32_t* r, uint32_t addr) {
    asm volatile("ldmatrix.sync.aligned.m8n8.x4.shared.b16 {%0,%1,%2,%3}, [%4];"
                 : "=r"(r[0]), "=r"(r[1]), "=r"(r[2]), "=r"(r[3]) : "r"(addr));
}

__device__ __forceinline__ void mma16816(float* c, const uint32_t* a,
                                         uint32_t b0, uint32_t b1) {
    asm volatile(
        "mma.sync.aligned.m16n8k16.row.col.f32.bf16.bf16.f32 "
        "{%0,%1,%2,%3}, {%4,%5,%6,%7}, {%8,%9}, {%0,%1,%2,%3};"
        : "+f"(c[0]), "+f"(c[1]), "+f"(c[2]), "+f"(c[3])
        : "r"(a[0]), "r"(a[1]), "r"(a[2]), "r"(a[3]), "r"(b0), "r"(b1));
}

__device__ __forceinline__ void load_tile(char* dst, int row0, int tid)
{
    #pragma unroll
    for (int it = 0; it < 16; it++) {
        int chunk = tid + it * 256;
        int r   = chunk >> 5;
        int c16 = chunk & 31;
        uint4 v = *(const uint4*)(g_Fb + (size_t)(row0 + r) * CD + c16 * 8);
        *(uint4*)(dst + r * PITCHB + c16 * 16) = v;
    }
}

// ---------------------------------------------------------------------------
// Kernel 2: upper-triangular tile GEMM with fused SupCon-neg epilogue.
// Neg tiles (labels differ): accumulate exp(l) row/col sums into g_neg,
// nothing written to g_dot. Pos tiles (labels equal): write tile (and its
// transpose for off-diagonal) to g_dot.
// ---------------------------------------------------------------------------
__global__ __launch_bounds__(256)
void gram_fused_kernel(const int* __restrict__ labels)
{
    extern __shared__ char smem[];
    char*  At = smem;
    char*  Bt = smem + TILE_BYTES;
    float* s_rowneg = (float*)(smem + OFF_ROWNEG);
    float* s_colneg = (float*)(smem + OFF_COLNEG);

    const int tid = threadIdx.x;
    const int wid = tid >> 5;
    const int lid = tid & 31;

    // decode upper-triangular tile index -> (I, J), I <= J
    int rem = blockIdx.x, I = 0;
    #pragma unroll 1
    while (rem >= NT - I) { rem -= NT - I; I++; }
    const int J  = I + rem;
    const int i0 = I * TM;
    const int j0 = J * TN;
    const int la = labels[i0 >> 8];
    const int lb = labels[j0 >> 8];

    if (tid < 128) { s_rowneg[tid] = 0.0f; s_colneg[tid] = 0.0f; }

    load_tile(At, i0, tid);
    load_tile(Bt, j0, tid);
    __syncthreads();

    const int wm = (wid & 3) * 32;
    const int wn = (wid >> 2) * 64;
    const uint32_t a_base = smem_u32(At) + (wm + (lid & 15)) * PITCHB + (lid >> 4) * 16;
    const uint32_t b_base = smem_u32(Bt) + (wn + (lid & 15)) * PITCHB + (lid >> 4) * 16;

    float acc[2][8][4];
    #pragma unroll
    for (int mi = 0; mi < 2; mi++)
        #pragma unroll
        for (int nj = 0; nj < 8; nj++)
            #pragma unroll
            for (int q = 0; q < 4; q++) acc[mi][nj][q] = 0.0f;

    #pragma unroll
    for (int ks = 0; ks < 16; ks++) {
        const int kb = ks * 32;
        uint32_t a[2][4], b[4][4];
        #pragma unroll
        for (int mi = 0; mi < 2; mi++)
            ldsm_x4(a[mi], a_base + mi * 16 * PITCHB + kb);
        #pragma unroll
        for (int nb = 0; nb < 4; nb++)
            ldsm_x4(b[nb], b_base + nb * 16 * PITCHB + kb);
        #pragma unroll
        for (int mi = 0; mi < 2; mi++)
            #pragma unroll
            for (int nj = 0; nj < 8; nj++)
                mma16816(acc[mi][nj], a[mi],
                         b[nj >> 1][nj & 1], b[nj >> 1][2 + (nj & 1)]);
    }

    if (la != lb) {
        // ---- negative tile: accumulate exp(dot - SHIFT) row & col sums ----
        float cs0[8], cs1[8];
        #pragma unroll
        for (int nj = 0; nj < 8; nj++) { cs0[nj] = 0.0f; cs1[nj] = 0.0f; }

        #pragma unroll
        for (int mi = 0; mi < 2; mi++) {
            float rs0 = 0.0f, rs1 = 0.0f;
            #pragma unroll
            for (int nj = 0; nj < 8; nj++) {
                float e0 = __expf(INV_TEMP * acc[mi][nj][0] - SHIFT);
                float e1 = __expf(INV_TEMP * acc[mi][nj][1] - SHIFT);
                float e2 = __expf(INV_TEMP * acc[mi][nj][2] - SHIFT);
                float e3 = __expf(INV_TEMP * acc[mi][nj][3] - SHIFT);
                rs0 += e0 + e1;  rs1 += e2 + e3;
                cs0[nj] += e0 + e2;  cs1[nj] += e1 + e3;
            }
            // reduce row sums across the 4 lanes sharing a row (lid&3)
            rs0 += __shfl_xor_sync(0xffffffffu, rs0, 1);
            rs0 += __shfl_xor_sync(0xffffffffu, rs0, 2);
            rs1 += __shfl_xor_sync(0xffffffffu, rs1, 1);
            rs1 += __shfl_xor_sync(0xffffffffu, rs1, 2);
            if ((lid & 3) == 0) {
                atomicAdd(&s_rowneg[wm + mi * 16 + (lid >> 2)],     rs0);
                atomicAdd(&s_rowneg[wm + mi * 16 + (lid >> 2) + 8], rs1);
            }
        }
        // reduce col sums across the 8 lanes sharing a column pair (lid>>2)
        #pragma unroll
        for (int nj = 0; nj < 8; nj++) {
            float v0 = cs0[nj], v1 = cs1[nj];
            v0 += __shfl_xor_sync(0xffffffffu, v0, 4);
            v0 += __shfl_xor_sync(0xffffffffu, v0, 8);
            v0 += __shfl_xor_sync(0xffffffffu, v0, 16);
            v1 += __shfl_xor_sync(0xffffffffu, v1, 4);
            v1 += __shfl_xor_sync(0xffffffffu, v1, 8);
            v1 += __shfl_xor_sync(0xffffffffu, v1, 16);
            if (lid < 4) {
                atomicAdd(&s_colneg[wn + nj * 8 + lid * 2],     v0);
                atomicAdd(&s_colneg[wn + nj * 8 + lid * 2 + 1], v1);
            }
        }
        __syncthreads();
        if (tid < 128)       atomicAdd(&g_neg[i0 + tid],       s_rowneg[tid]);
        else                 atomicAdd(&g_neg[j0 + tid - 128], s_colneg[tid - 128]);
    } else {
        // ---- positive tile: materialize dot values in g_dot ----
        #pragma unroll
        for (int mi = 0; mi < 2; mi++) {
            #pragma unroll
            for (int nj = 0; nj < 8; nj++) {
                int r = i0 + wm + mi * 16 + (lid >> 2);
                int c = j0 + wn + nj * 8 + (lid & 3) * 2;
                float2 v0 = make_float2(INV_TEMP * acc[mi][nj][0],
                                        INV_TEMP * acc[mi][nj][1]);
                float2 v1 = make_float2(INV_TEMP * acc[mi][nj][2],
                                        INV_TEMP * acc[mi][nj][3]);
                *(float2*)&g_dot[(size_t)r * TV + c]       = v0;
                *(float2*)&g_dot[(size_t)(r + 8) * TV + c] = v1;
            }
        }
        if (I != J) {
            // stage + transposed write (reuse At region; all warps done with it)
            __syncthreads();
            float* stage = (float*)At;
            #pragma unroll
            for (int mi = 0; mi < 2; mi++) {
                #pragma unroll
                for (int nj = 0; nj < 8; nj++) {
                    int r = wm + mi * 16 + (lid >> 2);
                    int c = wn + nj * 8 + (lid & 3) * 2;
                    stage[r * STAGE_PITCH + c]           = INV_TEMP * acc[mi][nj][0];
                    stage[r * STAGE_PITCH + c + 1]       = INV_TEMP * acc[mi][nj][1];
                    stage[(r + 8) * STAGE_PITCH + c]     = INV_TEMP * acc[mi][nj][2];
                    stage[(r + 8) * STAGE_PITCH + c + 1] = INV_TEMP * acc[mi][nj][3];
                }
            }
            __syncthreads();
            float* dstT = &g_dot[(size_t)j0 * TV + i0];
            #pragma unroll 4
            for (int idx = tid; idx < TM * TN; idx += 256) {
                int r = idx & 127;           // fast dim -> coalesced column of D^T
                int c = idx >> 7;
                dstT[(size_t)c * TV + r] = stage[r * STAGE_PITCH + c];
            }
        }
    }
}

// ---------------------------------------------------------------------------
// Kernel 3: positive pass. One block per row; reads only same-label blocks.
// ---------------------------------------------------------------------------
__global__ __launch_bounds__(256) void pospass_kernel(const int* __restrict__ labels,
                                                      float* __restrict__ out)
{
    __shared__ int   labs[TT];
    __shared__ float red[256];

    const int tid = threadIdx.x;
    const int i   = blockIdx.x;
    if (tid < TT) labs[tid] = labels[tid];
    __syncthreads();

    const int li   = labs[i >> 8];
    const float ng = g_neg[i];
    const float* row = g_dot + (size_t)i * TV;

    float psum = 0.0f;
    int   pcnt = 0;
    #pragma unroll 1
    for (int t = 0; t < TT; t++) {
        if (labs[t] != li) continue;
        int j = t * VV + tid;
        float d = row[j];
        if (j != i) {
            float l = d - SHIFT;
            psum += l - logf(__expf(l) + ng);
            pcnt++;
        }
    }

    red[tid] = psum;
    __syncthreads();
    #pragma unroll
    for (int ofs = 128; ofs > 0; ofs >>= 1) {
        if (tid < ofs) red[tid] += red[tid + ofs];
        __syncthreads();
    }
    float psum_tot = red[0];
    __syncthreads();
    red[tid] = (float)pcnt;
    __syncthreads();
    #pragma unroll
    for (int ofs = 128; ofs > 0; ofs >>= 1) {
        if (tid < ofs) red[tid] += red[tid + ofs];
        __syncthreads();
    }
    if (tid == 0) {
        float pcnt_tot = red[0];
        float mean_lp  = psum_tot / fmaxf(pcnt_tot, 1e-10f);
        atomicAdd(out, -mean_lp / (float)TV);
    }
}

// ---------------------------------------------------------------------------
extern "C" void kernel_launch(void* const* d_in, const int* in_sizes, int n_in,
                              void* d_out, int out_size)
{
    const float* features    = (const float*)d_in[0];
    const int*   batch_inds  = (const int*)d_in[1];
    const int*   sample_inds = (const int*)d_in[2];
    const int*   labels      = (const int*)d_in[3];
    float*       out         = (float*)d_out;

    cudaFuncSetAttribute(gram_fused_kernel,
                         cudaFuncAttributeMaxDynamicSharedMemorySize, SMEM_TOTAL);

    zero_kernel<<<TV / 256, 256>>>(out);
    gather_norm_kernel<<<TV, 256>>>(features, batch_inds, sample_inds);
    gram_fused_kernel<<<NT * (NT + 1) / 2, 256, SMEM_TOTAL>>>(labels);
    pospass_kernel<<<TV, 256>>>(labels, out);
}